// round 14
// baseline (speedup 1.0000x reference)
#include <cuda_runtime.h>
#include <cstddef>
#include <cstdint>

#define NF 1025
#define NM 128
#define NB 4
#define TT 1024
#define ROWS 4
#define NTHREADS 256
#define ITERS 20
#define NBLOCKS ((NB * TT) / ROWS)   // 1024
#define NGR 256
#define LISTCAP 1024
#define NDIFF 131
#define DUMMY 1024                   // zero slot in s_p (never written by P1)
#define PREP_BLOCKS 129              // 129 blocks x 8 warps >= 1025 freqs

typedef unsigned long long u64;

#define F2FMA(d,a,b,c) asm("fma.rn.f32x2 %0, %1, %2, %3;" : "=l"(d) : "l"(a), "l"(b), "l"(c))
#define F2MUL(d,a,b)   asm("mul.rn.f32x2 %0, %1, %2;"     : "=l"(d) : "l"(a), "l"(b))
#define F2ADD(d,a,b)   asm("add.rn.f32x2 %0, %1, %2;"     : "=l"(d) : "l"(a), "l"(b))
#define PK2(d,lo,hi)   asm("mov.b64 %0, {%1, %2};" : "=l"(d) : "f"(lo), "f"(hi))
#define UPK2(lo,hi,s)  asm("mov.b64 {%0, %1}, %2;" : "=f"(lo), "=f"(hi) : "l"(s))

__device__ float  g_w0[NF];
__device__ float  g_w1[NF];
__device__ int    g_mi[NF];
__device__ float4 g_wv[NGR * 4];        // [g][c] channel weight vectors
__device__ int    g_mb[NGR];            // base mel | nzm<<8 per granule
__device__ unsigned short g_list[LISTCAP];  // term idx = c*NGR + g, per mel
__device__ int    g_redmeta[NM];        // start | count<<16
__device__ unsigned g_done;             // last-block counter (reset each launch)

// ---------------------------------------------------------------------------
// Fused prep: 129 blocks x 8 warps handle one freq row each (coalesced
// float4 + warp-min + shfl weights); the LAST block to finish then runs the
// schedule stage (granule weight blocks + masks + per-mel term lists) and
// resets the counter so the kernel is graph-replay deterministic.
// ---------------------------------------------------------------------------
__global__ void prep_all(const float* __restrict__ fb) {
    const int t    = threadIdx.x;
    const int wid  = t >> 5;
    const int lane = t & 31;
    const int gw   = blockIdx.x * 8 + wid;

    // ---- stage 1: per-freq sparse structure ----
    if (gw < NF) {
        const float4 v = ((const float4*)(fb + (size_t)gw * NM))[lane];
        int cand = 128;
        if (v.w > 0.0f) cand = lane * 4 + 3;
        if (v.z > 0.0f) cand = lane * 4 + 2;
        if (v.y > 0.0f) cand = lane * 4 + 1;
        if (v.x > 0.0f) cand = lane * 4;
#pragma unroll
        for (int o = 16; o; o >>= 1) {
            int other = __shfl_xor_sync(0xFFFFFFFFu, cand, o);
            cand = (other < cand) ? other : cand;
        }
        int mi = cand;
        float w0 = 0.0f, w1 = 0.0f;
        if (mi < 128) {
            int e0 = mi & 3;
            float my0 = (e0 == 0) ? v.x : (e0 == 1) ? v.y : (e0 == 2) ? v.z : v.w;
            w0 = __shfl_sync(0xFFFFFFFFu, my0, mi >> 2);
            int m1 = mi + 1;
            if (m1 < 128) {
                int e1 = m1 & 3;
                float my1 = (e1 == 0) ? v.x : (e1 == 1) ? v.y : (e1 == 2) ? v.z : v.w;
                w1 = __shfl_sync(0xFFFFFFFFu, my1, m1 >> 2);
            }
        } else mi = 0;
        if (lane == 0) { g_mi[gw] = mi; g_w0[gw] = w0; g_w1[gw] = w1; }
    }

    // ---- last-block election (release: fence before count) ----
    __syncthreads();
    __threadfence();
    __shared__ int s_is_last;
    if (t == 0) {
        unsigned old = atomicAdd(&g_done, 1u);
        s_is_last = (old == PREP_BLOCKS - 1) ? 1 : 0;
    }
    __syncthreads();
    if (!s_is_last) return;
    __threadfence();   // acquire: all blocks' g_mi/g_w0/g_w1 now visible

    // ---- stage 2: schedule (256 threads, original prep_sched body) ----
    __shared__ int s_mb[NGR];
    __shared__ unsigned char s_nzm[NGR];
    __shared__ int s_cnt[NM];
    __shared__ int s_start[NM];

    {
        const int g = t;
        const int mb = g_mi[4 * g];
        float wv[4][4];
#pragma unroll
        for (int c = 0; c < 4; c++)
#pragma unroll
            for (int e = 0; e < 4; e++) wv[c][e] = 0.0f;
#pragma unroll
        for (int e = 0; e < 4; e++) {
            int f = 4 * g + e;
            int c0 = g_mi[f] - mb;
            if (c0 < 0) c0 = 0;
            if (c0 > 2) c0 = 2;
            wv[c0][e]     += g_w0[f];
            wv[c0 + 1][e] += g_w1[f];
        }
        unsigned char nz = 0;
#pragma unroll
        for (int c = 0; c < 4; c++) {
            float4 v = make_float4(wv[c][0], wv[c][1], wv[c][2], wv[c][3]);
            g_wv[g * 4 + c] = v;
            if (v.x != 0.0f || v.y != 0.0f || v.z != 0.0f || v.w != 0.0f)
                nz |= (unsigned char)(1u << c);
        }
        s_mb[g] = mb;
        s_nzm[g] = nz;
        g_mb[g] = mb | ((int)nz << 8);
    }
    __syncthreads();

    if (t < NM) {
        int n = 0;
        for (int g = 0; g < NGR; g++) {
            int c = t - s_mb[g];
            if (c >= 0 && c < 4 && ((s_nzm[g] >> c) & 1)) n++;
        }
        s_cnt[t] = n;
    }
    __syncthreads();
    if (t == 0) {
        int acc = 0;
        for (int m = 0; m < NM; m++) { s_start[m] = acc; acc += s_cnt[m]; }
    }
    __syncthreads();
    if (t < NM) {
        int idx = s_start[t];
        g_redmeta[t] = s_start[t] | (s_cnt[t] << 16);
        for (int g = 0; g < NGR; g++) {   // g-ascending: deterministic order
            int c = t - s_mb[g];
            if (c >= 0 && c < 4 && ((s_nzm[g] >> c) & 1))
                g_list[idx++] = (unsigned short)(c * NGR + g);
        }
    }

    // ---- reset counter for next graph replay (strictly after last use) ----
    __syncthreads();
    if (t == 0) atomicExch(&g_done, 0u);
}

// ---------------------------------------------------------------------------
// Main (frozen R13, best measured): 20 SGD iterations, 4 rows/CTA, packed
// f32x2 state + weights, register-hoisted unrolled P2, predicated P1 stores.
// ---------------------------------------------------------------------------
__global__ __launch_bounds__(NTHREADS, 3)
void invmel_main(const float* __restrict__ melspec,
                 const float* __restrict__ spec_init,
                 float* __restrict__ out) {
    __shared__ float4 s_p[4 * NGR + 1];       // partials [c][g] x 4 rows + zero slot
    __shared__ float4 s_diff[NDIFF];          // diff[mel] x 4 rows

    const float cINV = 2.0f / (float)(NB * TT);

    const int tid  = threadIdx.x;
    const int row0 = blockIdx.x * ROWS;
    const int b    = row0 / TT;
    const int t0   = row0 % TT;

    // ---- packed weights: wpk[c][e] = (w, w) ----
    u64 wpk[4][4];
#pragma unroll
    for (int c = 0; c < 4; c++) {
        float4 v = g_wv[tid * 4 + c];
        PK2(wpk[c][0], v.x, v.x);
        PK2(wpk[c][1], v.y, v.y);
        PK2(wpk[c][2], v.z, v.z);
        PK2(wpk[c][3], v.w, v.w);
    }
    const int gmv = g_mb[tid];
    const int mb  = gmv & 255;
    const unsigned nzm = (unsigned)(gmv >> 8);

    // ---- packed row state: (r0,r1) and (r2,r3) pairs ----
    u64 sp01[4], sp23[4], rb01[4], rb23[4];
#pragma unroll
    for (int e = 0; e < 4; e++) {
        float v0 = spec_init[(size_t)(row0 + 0) * NF + 4 * tid + e];
        float v1 = spec_init[(size_t)(row0 + 1) * NF + 4 * tid + e];
        float v2 = spec_init[(size_t)(row0 + 2) * NF + 4 * tid + e];
        float v3 = spec_init[(size_t)(row0 + 3) * NF + 4 * tid + e];
        PK2(sp01[e], v0, v1);
        PK2(sp23[e], v2, v3);
        rb01[e] = 0ull;
        rb23[e] = 0ull;
    }
    u64 kMOM, kNINV, kNLR;
    PK2(kMOM, 0.9f, 0.9f);
    PK2(kNINV, -cINV, -cINV);
    PK2(kNLR, -0.3f, -0.3f);

    // ---- reducer identity: lane pair (2k,2k+1) of warp w -> mel k*8+w ----
    const int lane = tid & 31;
    const int wrp  = tid >> 5;
    const int mel  = (lane >> 1) * 8 + wrp;
    const bool evenlane = ((lane & 1) == 0);
    const int rm = g_redmeta[mel];
    const int rs = rm & 0xFFFF;
    const int rn = rm >> 16;
    const int h  = (rn + 1) >> 1;
    const int ts = evenlane ? rs : rs + h;
    const int te = evenlane ? rs + h : rs + rn;
    const float4* melp = (const float4*)&melspec[((size_t)b * NM + mel) * TT + t0];

    // ---- hoist this half-lane's term indices into registers ----
    unsigned short myi[8];
#pragma unroll
    for (int j = 0; j < 8; j++)
        myi[j] = (ts + j < te) ? __ldg(&g_list[ts + j]) : (unsigned short)DUMMY;
    uint4 Lx;
    Lx.x = (unsigned)myi[0] | ((unsigned)myi[1] << 16);
    Lx.y = (unsigned)myi[2] | ((unsigned)myi[3] << 16);
    Lx.z = (unsigned)myi[4] | ((unsigned)myi[5] << 16);
    Lx.w = (unsigned)myi[6] | ((unsigned)myi[7] << 16);

    if (tid == 0) s_p[DUMMY] = make_float4(0.f, 0.f, 0.f, 0.f);
    if (tid < NDIFF - NM) s_diff[NM + tid] = make_float4(0.f, 0.f, 0.f, 0.f);
    __syncthreads();

    for (int it = 0; it < ITERS; it++) {
        // ---- P1: channel partials; store only nonzero channels ----
#pragma unroll
        for (int c = 0; c < 4; c++) {
            u64 a01, a23;
            F2MUL(a01, wpk[c][0], sp01[0]);
            F2MUL(a23, wpk[c][0], sp23[0]);
#pragma unroll
            for (int e = 1; e < 4; e++) {
                F2FMA(a01, wpk[c][e], sp01[e], a01);
                F2FMA(a23, wpk[c][e], sp23[e], a23);
            }
            if (nzm & (1u << c)) {
                ulonglong2 stv; stv.x = a01; stv.y = a23;
                *(ulonglong2*)&s_p[c * NGR + tid] = stv;
            }
        }
        __syncthreads();

        // ---- P2: 8 pipelined LDS.128 + pairwise tree ----
        ulonglong2 q0 = *(const ulonglong2*)&s_p[Lx.x & 0xFFFF];
        ulonglong2 q1 = *(const ulonglong2*)&s_p[Lx.x >> 16];
        ulonglong2 q2 = *(const ulonglong2*)&s_p[Lx.y & 0xFFFF];
        ulonglong2 q3 = *(const ulonglong2*)&s_p[Lx.y >> 16];
        ulonglong2 q4 = *(const ulonglong2*)&s_p[Lx.z & 0xFFFF];
        ulonglong2 q5 = *(const ulonglong2*)&s_p[Lx.z >> 16];
        ulonglong2 q6 = *(const ulonglong2*)&s_p[Lx.w & 0xFFFF];
        ulonglong2 q7 = *(const ulonglong2*)&s_p[Lx.w >> 16];
        u64 a01, a23, tA, tB, tC, tD;
        F2ADD(tA, q0.x, q1.x); F2ADD(tB, q2.x, q3.x);
        F2ADD(tC, q4.x, q5.x); F2ADD(tD, q6.x, q7.x);
        F2ADD(tA, tA, tB);     F2ADD(tC, tC, tD);
        F2ADD(a01, tA, tC);
        F2ADD(tA, q0.y, q1.y); F2ADD(tB, q2.y, q3.y);
        F2ADD(tC, q4.y, q5.y); F2ADD(tD, q6.y, q7.y);
        F2ADD(tA, tA, tB);     F2ADD(tC, tC, tD);
        F2ADD(a23, tA, tC);

        float ax, ay, az, aw;
        UPK2(ax, ay, a01);
        UPK2(az, aw, a23);
        ax += __shfl_xor_sync(0xFFFFFFFFu, ax, 1);
        ay += __shfl_xor_sync(0xFFFFFFFFu, ay, 1);
        az += __shfl_xor_sync(0xFFFFFFFFu, az, 1);
        aw += __shfl_xor_sync(0xFFFFFFFFu, aw, 1);
        if (evenlane) {
            float4 mv = __ldg(melp);  // L1-resident after iter 0
            s_diff[mel] = make_float4(mv.x - ax, mv.y - ay, mv.z - az, mv.w - aw);
        }
        __syncthreads();

        // ---- P3: grad + momentum + clamp ----
        ulonglong2 d0 = *(const ulonglong2*)&s_diff[mb + 0];
        ulonglong2 d1 = *(const ulonglong2*)&s_diff[mb + 1];
        ulonglong2 d2 = *(const ulonglong2*)&s_diff[mb + 2];
        ulonglong2 d3 = *(const ulonglong2*)&s_diff[mb + 3];
#pragma unroll
        for (int e = 0; e < 4; e++) {
            u64 g01, g23;
            F2MUL(g01, wpk[0][e], d0.x);
            F2MUL(g23, wpk[0][e], d0.y);
            F2FMA(g01, wpk[1][e], d1.x, g01);
            F2FMA(g23, wpk[1][e], d1.y, g23);
            F2FMA(g01, wpk[2][e], d2.x, g01);
            F2FMA(g23, wpk[2][e], d2.y, g23);
            F2FMA(g01, wpk[3][e], d3.x, g01);
            F2FMA(g23, wpk[3][e], d3.y, g23);
            u64 t01, t23;
            F2MUL(t01, kNINV, g01);
            F2MUL(t23, kNINV, g23);
            F2FMA(rb01[e], kMOM, rb01[e], t01);
            F2FMA(rb23[e], kMOM, rb23[e], t23);
            u64 s01, s23;
            F2FMA(s01, kNLR, rb01[e], sp01[e]);
            F2FMA(s23, kNLR, rb23[e], sp23[e]);
            float lo, hi;
            UPK2(lo, hi, s01);
            PK2(sp01[e], fmaxf(lo, 0.0f), fmaxf(hi, 0.0f));
            UPK2(lo, hi, s23);
            PK2(sp23[e], fmaxf(lo, 0.0f), fmaxf(hi, 0.0f));
        }
        // no barrier: next P1 rewrites s_p (read before last barrier);
        // s_diff rewritten only after the next iteration's first barrier.
    }

    // ---- output: one 16B store per owned f ----
#pragma unroll
    for (int e = 0; e < 4; e++) {
        ulonglong2 v; v.x = sp01[e]; v.y = sp23[e];   // rows 0,1,2,3
        *(ulonglong2*)&out[((size_t)b * NF + 4 * tid + e) * TT + t0] = v;
    }
    if (tid < ROWS) {   // f = 1024: zero fb row -> passthrough of init (>=0)
        out[((size_t)b * NF + 1024) * TT + t0 + tid] =
            spec_init[(size_t)(row0 + tid) * NF + 1024];
    }
}

// ---------------------------------------------------------------------------
extern "C" void kernel_launch(void* const* d_in, const int* in_sizes, int n_in,
                              void* d_out, int out_size) {
    const float* melspec = nullptr;
    const float* spec_init = nullptr;
    const float* fb = nullptr;
    for (int i = 0; i < n_in; i++) {
        if (in_sizes[i] == NB * NM * TT)      melspec   = (const float*)d_in[i];
        else if (in_sizes[i] == NB * TT * NF) spec_init = (const float*)d_in[i];
        else if (in_sizes[i] == NF * NM)      fb        = (const float*)d_in[i];
    }
    float* out = (float*)d_out;

    prep_all<<<PREP_BLOCKS, NTHREADS>>>(fb);
    invmel_main<<<NBLOCKS, NTHREADS>>>(melspec, spec_init, out);
}

// round 15
// speedup vs baseline: 1.1240x; 1.1240x over previous
#include <cuda_runtime.h>
#include <cstddef>
#include <cstdint>

#define NF 1025
#define NM 128
#define NB 4
#define TT 1024
#define ROWS 4
#define NTHREADS 256
#define ITERS 20
#define NBLOCKS ((NB * TT) / ROWS)   // 1024
#define NGR 256
#define LISTCAP 1024
#define NDIFF 131
#define DUMMY 1024                   // zero slot in s_p (never written by P1)

typedef unsigned long long u64;

#define F2FMA(d,a,b,c) asm("fma.rn.f32x2 %0, %1, %2, %3;" : "=l"(d) : "l"(a), "l"(b), "l"(c))
#define F2MUL(d,a,b)   asm("mul.rn.f32x2 %0, %1, %2;"     : "=l"(d) : "l"(a), "l"(b))
#define F2ADD(d,a,b)   asm("add.rn.f32x2 %0, %1, %2;"     : "=l"(d) : "l"(a), "l"(b))
#define PK2(d,lo,hi)   asm("mov.b64 %0, {%1, %2};" : "=l"(d) : "f"(lo), "f"(hi))
#define UPK2(lo,hi,s)  asm("mov.b64 {%0, %1}, %2;" : "=f"(lo), "=f"(hi) : "l"(s))

__device__ float  g_w0[NF];
__device__ float  g_w1[NF];
__device__ int    g_mi[NF];
__device__ float4 g_wv[NGR * 4];        // [g][c] channel weight vectors
__device__ int    g_mb[NGR];            // base mel | nzm<<8 per granule
__device__ unsigned short g_list[LISTCAP];  // term idx = c*NGR + g, per mel
__device__ int    g_redmeta[NM];        // start | count<<16

// ---------------------------------------------------------------------------
// Prep 1 (fast, validated): warp per frequency row.
// ---------------------------------------------------------------------------
__global__ void prep_freq(const float* __restrict__ fb) {
    int gw   = (blockIdx.x * blockDim.x + threadIdx.x) >> 5;
    int lane = threadIdx.x & 31;
    if (gw >= NF) return;
    const float4 v = ((const float4*)(fb + (size_t)gw * NM))[lane];
    int cand = 128;
    if (v.w > 0.0f) cand = lane * 4 + 3;
    if (v.z > 0.0f) cand = lane * 4 + 2;
    if (v.y > 0.0f) cand = lane * 4 + 1;
    if (v.x > 0.0f) cand = lane * 4;
#pragma unroll
    for (int o = 16; o; o >>= 1) {
        int other = __shfl_xor_sync(0xFFFFFFFFu, cand, o);
        cand = (other < cand) ? other : cand;
    }
    int mi = cand;
    float w0 = 0.0f, w1 = 0.0f;
    if (mi < 128) {
        int e0 = mi & 3;
        float my0 = (e0 == 0) ? v.x : (e0 == 1) ? v.y : (e0 == 2) ? v.z : v.w;
        w0 = __shfl_sync(0xFFFFFFFFu, my0, mi >> 2);
        int m1 = mi + 1;
        if (m1 < 128) {
            int e1 = m1 & 3;
            float my1 = (e1 == 0) ? v.x : (e1 == 1) ? v.y : (e1 == 2) ? v.z : v.w;
            w1 = __shfl_sync(0xFFFFFFFFu, my1, m1 >> 2);
        }
    } else mi = 0;
    if (lane == 0) { g_mi[gw] = mi; g_w0[gw] = w0; g_w1[gw] = w1; }
}

// ---------------------------------------------------------------------------
// Prep 2 (single block): granule weight blocks + per-mel term lists.
// mb(g) is non-decreasing, so each mel's contributing granules are a
// contiguous range found by binary search -> short loops (was O(256)).
// Emission order (g-ascending) identical to prior rounds: bit-stable output.
// ---------------------------------------------------------------------------
__global__ void prep_sched() {
    __shared__ int s_mb[NGR];
    __shared__ unsigned char s_nzm[NGR];
    __shared__ int s_cnt[NM];
    __shared__ int s_start[NM];
    const int t = threadIdx.x;

    {   // per-granule 4-channel weights + nonzero mask
        const int g = t;
        const int mb = g_mi[4 * g];
        float wv[4][4];
#pragma unroll
        for (int c = 0; c < 4; c++)
#pragma unroll
            for (int e = 0; e < 4; e++) wv[c][e] = 0.0f;
#pragma unroll
        for (int e = 0; e < 4; e++) {
            int f = 4 * g + e;
            int c0 = g_mi[f] - mb;
            if (c0 < 0) c0 = 0;
            if (c0 > 2) c0 = 2;
            wv[c0][e]     += g_w0[f];
            wv[c0 + 1][e] += g_w1[f];
        }
        unsigned char nz = 0;
#pragma unroll
        for (int c = 0; c < 4; c++) {
            float4 v = make_float4(wv[c][0], wv[c][1], wv[c][2], wv[c][3]);
            g_wv[g * 4 + c] = v;
            if (v.x != 0.0f || v.y != 0.0f || v.z != 0.0f || v.w != 0.0f)
                nz |= (unsigned char)(1u << c);
        }
        s_mb[g] = mb;
        s_nzm[g] = nz;
        g_mb[g] = mb | ((int)nz << 8);
    }
    __syncthreads();

    // per-mel contiguous granule range via binary search over monotone s_mb
    int glo = 0, ghi = 0;
    if (t < NM) {
        const int m = t;
        int a = 0, b = NGR;
        while (a < b) {                     // first g with mb[g] >= m-3
            int mid = (a + b) >> 1;
            if (s_mb[mid] < m - 3) a = mid + 1; else b = mid;
        }
        glo = a;
        b = NGR;                            // first g with mb[g] > m
        while (a < b) {
            int mid = (a + b) >> 1;
            if (s_mb[mid] <= m) a = mid + 1; else b = mid;
        }
        ghi = a;
        int n = 0;
        for (int g = glo; g < ghi; g++) {
            int c = m - s_mb[g];
            if (c >= 0 && c < 4 && ((s_nzm[g] >> c) & 1)) n++;
        }
        s_cnt[t] = n;
    }
    __syncthreads();
    if (t == 0) {
        int acc = 0;
        for (int m = 0; m < NM; m++) { s_start[m] = acc; acc += s_cnt[m]; }
    }
    __syncthreads();
    if (t < NM) {
        const int m = t;
        int idx = s_start[t];
        g_redmeta[t] = s_start[t] | (s_cnt[t] << 16);
        for (int g = glo; g < ghi; g++) {   // g-ascending: deterministic order
            int c = m - s_mb[g];
            if (c >= 0 && c < 4 && ((s_nzm[g] >> c) & 1))
                g_list[idx++] = (unsigned short)(c * NGR + g);
        }
    }
}

// ---------------------------------------------------------------------------
// Main (frozen R13, best measured 89.0us): 20 SGD iterations, 4 rows/CTA,
// packed f32x2 state + weights, register-hoisted unrolled P2, predicated
// P1 stores, occupancy 3.
// ---------------------------------------------------------------------------
__global__ __launch_bounds__(NTHREADS, 3)
void invmel_main(const float* __restrict__ melspec,
                 const float* __restrict__ spec_init,
                 float* __restrict__ out) {
    __shared__ float4 s_p[4 * NGR + 1];       // partials [c][g] x 4 rows + zero slot
    __shared__ float4 s_diff[NDIFF];          // diff[mel] x 4 rows

    const float cINV = 2.0f / (float)(NB * TT);

    const int tid  = threadIdx.x;
    const int row0 = blockIdx.x * ROWS;
    const int b    = row0 / TT;
    const int t0   = row0 % TT;

    // ---- packed weights: wpk[c][e] = (w, w) ----
    u64 wpk[4][4];
#pragma unroll
    for (int c = 0; c < 4; c++) {
        float4 v = g_wv[tid * 4 + c];
        PK2(wpk[c][0], v.x, v.x);
        PK2(wpk[c][1], v.y, v.y);
        PK2(wpk[c][2], v.z, v.z);
        PK2(wpk[c][3], v.w, v.w);
    }
    const int gmv = g_mb[tid];
    const int mb  = gmv & 255;
    const unsigned nzm = (unsigned)(gmv >> 8);

    // ---- packed row state: (r0,r1) and (r2,r3) pairs ----
    u64 sp01[4], sp23[4], rb01[4], rb23[4];
#pragma unroll
    for (int e = 0; e < 4; e++) {
        float v0 = spec_init[(size_t)(row0 + 0) * NF + 4 * tid + e];
        float v1 = spec_init[(size_t)(row0 + 1) * NF + 4 * tid + e];
        float v2 = spec_init[(size_t)(row0 + 2) * NF + 4 * tid + e];
        float v3 = spec_init[(size_t)(row0 + 3) * NF + 4 * tid + e];
        PK2(sp01[e], v0, v1);
        PK2(sp23[e], v2, v3);
        rb01[e] = 0ull;
        rb23[e] = 0ull;
    }
    u64 kMOM, kNINV, kNLR;
    PK2(kMOM, 0.9f, 0.9f);
    PK2(kNINV, -cINV, -cINV);
    PK2(kNLR, -0.3f, -0.3f);

    // ---- reducer identity: lane pair (2k,2k+1) of warp w -> mel k*8+w ----
    const int lane = tid & 31;
    const int wrp  = tid >> 5;
    const int mel  = (lane >> 1) * 8 + wrp;
    const bool evenlane = ((lane & 1) == 0);
    const int rm = g_redmeta[mel];
    const int rs = rm & 0xFFFF;
    const int rn = rm >> 16;
    const int h  = (rn + 1) >> 1;
    const int ts = evenlane ? rs : rs + h;
    const int te = evenlane ? rs + h : rs + rn;
    const float4* melp = (const float4*)&melspec[((size_t)b * NM + mel) * TT + t0];

    // ---- hoist this half-lane's term indices into registers ----
    unsigned short myi[8];
#pragma unroll
    for (int j = 0; j < 8; j++)
        myi[j] = (ts + j < te) ? __ldg(&g_list[ts + j]) : (unsigned short)DUMMY;
    uint4 Lx;
    Lx.x = (unsigned)myi[0] | ((unsigned)myi[1] << 16);
    Lx.y = (unsigned)myi[2] | ((unsigned)myi[3] << 16);
    Lx.z = (unsigned)myi[4] | ((unsigned)myi[5] << 16);
    Lx.w = (unsigned)myi[6] | ((unsigned)myi[7] << 16);

    if (tid == 0) s_p[DUMMY] = make_float4(0.f, 0.f, 0.f, 0.f);
    if (tid < NDIFF - NM) s_diff[NM + tid] = make_float4(0.f, 0.f, 0.f, 0.f);
    __syncthreads();

    for (int it = 0; it < ITERS; it++) {
        // ---- P1: channel partials; store only nonzero channels ----
#pragma unroll
        for (int c = 0; c < 4; c++) {
            u64 a01, a23;
            F2MUL(a01, wpk[c][0], sp01[0]);
            F2MUL(a23, wpk[c][0], sp23[0]);
#pragma unroll
            for (int e = 1; e < 4; e++) {
                F2FMA(a01, wpk[c][e], sp01[e], a01);
                F2FMA(a23, wpk[c][e], sp23[e], a23);
            }
            if (nzm & (1u << c)) {
                ulonglong2 stv; stv.x = a01; stv.y = a23;
                *(ulonglong2*)&s_p[c * NGR + tid] = stv;
            }
        }
        __syncthreads();

        // ---- P2: 8 pipelined LDS.128 + pairwise tree ----
        ulonglong2 q0 = *(const ulonglong2*)&s_p[Lx.x & 0xFFFF];
        ulonglong2 q1 = *(const ulonglong2*)&s_p[Lx.x >> 16];
        ulonglong2 q2 = *(const ulonglong2*)&s_p[Lx.y & 0xFFFF];
        ulonglong2 q3 = *(const ulonglong2*)&s_p[Lx.y >> 16];
        ulonglong2 q4 = *(const ulonglong2*)&s_p[Lx.z & 0xFFFF];
        ulonglong2 q5 = *(const ulonglong2*)&s_p[Lx.z >> 16];
        ulonglong2 q6 = *(const ulonglong2*)&s_p[Lx.w & 0xFFFF];
        ulonglong2 q7 = *(const ulonglong2*)&s_p[Lx.w >> 16];
        u64 a01, a23, tA, tB, tC, tD;
        F2ADD(tA, q0.x, q1.x); F2ADD(tB, q2.x, q3.x);
        F2ADD(tC, q4.x, q5.x); F2ADD(tD, q6.x, q7.x);
        F2ADD(tA, tA, tB);     F2ADD(tC, tC, tD);
        F2ADD(a01, tA, tC);
        F2ADD(tA, q0.y, q1.y); F2ADD(tB, q2.y, q3.y);
        F2ADD(tC, q4.y, q5.y); F2ADD(tD, q6.y, q7.y);
        F2ADD(tA, tA, tB);     F2ADD(tC, tC, tD);
        F2ADD(a23, tA, tC);

        float ax, ay, az, aw;
        UPK2(ax, ay, a01);
        UPK2(az, aw, a23);
        ax += __shfl_xor_sync(0xFFFFFFFFu, ax, 1);
        ay += __shfl_xor_sync(0xFFFFFFFFu, ay, 1);
        az += __shfl_xor_sync(0xFFFFFFFFu, az, 1);
        aw += __shfl_xor_sync(0xFFFFFFFFu, aw, 1);
        if (evenlane) {
            float4 mv = __ldg(melp);  // L1-resident after iter 0
            s_diff[mel] = make_float4(mv.x - ax, mv.y - ay, mv.z - az, mv.w - aw);
        }
        __syncthreads();

        // ---- P3: grad + momentum + clamp ----
        ulonglong2 d0 = *(const ulonglong2*)&s_diff[mb + 0];
        ulonglong2 d1 = *(const ulonglong2*)&s_diff[mb + 1];
        ulonglong2 d2 = *(const ulonglong2*)&s_diff[mb + 2];
        ulonglong2 d3 = *(const ulonglong2*)&s_diff[mb + 3];
#pragma unroll
        for (int e = 0; e < 4; e++) {
            u64 g01, g23;
            F2MUL(g01, wpk[0][e], d0.x);
            F2MUL(g23, wpk[0][e], d0.y);
            F2FMA(g01, wpk[1][e], d1.x, g01);
            F2FMA(g23, wpk[1][e], d1.y, g23);
            F2FMA(g01, wpk[2][e], d2.x, g01);
            F2FMA(g23, wpk[2][e], d2.y, g23);
            F2FMA(g01, wpk[3][e], d3.x, g01);
            F2FMA(g23, wpk[3][e], d3.y, g23);
            u64 t01, t23;
            F2MUL(t01, kNINV, g01);
            F2MUL(t23, kNINV, g23);
            F2FMA(rb01[e], kMOM, rb01[e], t01);
            F2FMA(rb23[e], kMOM, rb23[e], t23);
            u64 s01, s23;
            F2FMA(s01, kNLR, rb01[e], sp01[e]);
            F2FMA(s23, kNLR, rb23[e], sp23[e]);
            float lo, hi;
            UPK2(lo, hi, s01);
            PK2(sp01[e], fmaxf(lo, 0.0f), fmaxf(hi, 0.0f));
            UPK2(lo, hi, s23);
            PK2(sp23[e], fmaxf(lo, 0.0f), fmaxf(hi, 0.0f));
        }
        // no barrier: next P1 rewrites s_p (read before last barrier);
        // s_diff rewritten only after the next iteration's first barrier.
    }

    // ---- output: one 16B store per owned f ----
#pragma unroll
    for (int e = 0; e < 4; e++) {
        ulonglong2 v; v.x = sp01[e]; v.y = sp23[e];   // rows 0,1,2,3
        *(ulonglong2*)&out[((size_t)b * NF + 4 * tid + e) * TT + t0] = v;
    }
    if (tid < ROWS) {   // f = 1024: zero fb row -> passthrough of init (>=0)
        out[((size_t)b * NF + 1024) * TT + t0 + tid] =
            spec_init[(size_t)(row0 + tid) * NF + 1024];
    }
}

// ---------------------------------------------------------------------------
extern "C" void kernel_launch(void* const* d_in, const int* in_sizes, int n_in,
                              void* d_out, int out_size) {
    const float* melspec = nullptr;
    const float* spec_init = nullptr;
    const float* fb = nullptr;
    for (int i = 0; i < n_in; i++) {
        if (in_sizes[i] == NB * NM * TT)      melspec   = (const float*)d_in[i];
        else if (in_sizes[i] == NB * TT * NF) spec_init = (const float*)d_in[i];
        else if (in_sizes[i] == NF * NM)      fb        = (const float*)d_in[i];
    }
    float* out = (float*)d_out;

    prep_freq<<<(NF * 32 + 255) / 256, 256>>>(fb);
    prep_sched<<<1, NTHREADS>>>();
    invmel_main<<<NBLOCKS, NTHREADS>>>(melspec, spec_init, out);
}

// round 16
// speedup vs baseline: 1.1274x; 1.0030x over previous
#include <cuda_runtime.h>
#include <cstddef>
#include <cstdint>

#define NF 1025
#define NM 128
#define NB 4
#define TT 1024
#define ROWS 4
#define NTHREADS 256
#define ITERS 20
#define NBLOCKS ((NB * TT) / ROWS)   // 1024
#define NGR 256
#define LISTCAP 1024
#define NDIFF 131
#define DUMMY 1024                   // zero slot in s_p (never written by P1)

typedef unsigned long long u64;

#define F2FMA(d,a,b,c) asm("fma.rn.f32x2 %0, %1, %2, %3;" : "=l"(d) : "l"(a), "l"(b), "l"(c))
#define F2MUL(d,a,b)   asm("mul.rn.f32x2 %0, %1, %2;"     : "=l"(d) : "l"(a), "l"(b))
#define F2ADD(d,a,b)   asm("add.rn.f32x2 %0, %1, %2;"     : "=l"(d) : "l"(a), "l"(b))
#define PK2(d,lo,hi)   asm("mov.b64 %0, {%1, %2};" : "=l"(d) : "f"(lo), "f"(hi))
#define UPK2(lo,hi,s)  asm("mov.b64 {%0, %1}, %2;" : "=f"(lo), "=f"(hi) : "l"(s))

__device__ float  g_w0[NF];
__device__ float  g_w1[NF];
__device__ int    g_mi[NF];
__device__ float4 g_wv[NGR * 4];        // [g][c] channel weight vectors
__device__ int    g_mb[NGR];            // base mel | nzm<<8 per granule
__device__ unsigned short g_list[LISTCAP];  // term idx = c*NGR + g, per mel
__device__ int    g_redmeta[NM];        // start | count<<16

// ---------------------------------------------------------------------------
// Prep 1 (fast, validated): warp per frequency row.
// ---------------------------------------------------------------------------
__global__ void prep_freq(const float* __restrict__ fb) {
    int gw   = (blockIdx.x * blockDim.x + threadIdx.x) >> 5;
    int lane = threadIdx.x & 31;
    if (gw >= NF) return;
    const float4 v = ((const float4*)(fb + (size_t)gw * NM))[lane];
    int cand = 128;
    if (v.w > 0.0f) cand = lane * 4 + 3;
    if (v.z > 0.0f) cand = lane * 4 + 2;
    if (v.y > 0.0f) cand = lane * 4 + 1;
    if (v.x > 0.0f) cand = lane * 4;
#pragma unroll
    for (int o = 16; o; o >>= 1) {
        int other = __shfl_xor_sync(0xFFFFFFFFu, cand, o);
        cand = (other < cand) ? other : cand;
    }
    int mi = cand;
    float w0 = 0.0f, w1 = 0.0f;
    if (mi < 128) {
        int e0 = mi & 3;
        float my0 = (e0 == 0) ? v.x : (e0 == 1) ? v.y : (e0 == 2) ? v.z : v.w;
        w0 = __shfl_sync(0xFFFFFFFFu, my0, mi >> 2);
        int m1 = mi + 1;
        if (m1 < 128) {
            int e1 = m1 & 3;
            float my1 = (e1 == 0) ? v.x : (e1 == 1) ? v.y : (e1 == 2) ? v.z : v.w;
            w1 = __shfl_sync(0xFFFFFFFFu, my1, m1 >> 2);
        }
    } else mi = 0;
    if (lane == 0) { g_mi[gw] = mi; g_w0[gw] = w0; g_w1[gw] = w1; }
}

// ---------------------------------------------------------------------------
// Prep 2 (single block, PDL secondary): binary-search schedule (R15).
// Grid-syncs before touching prep_freq outputs.
// ---------------------------------------------------------------------------
__global__ void prep_sched() {
    __shared__ int s_mb[NGR];
    __shared__ unsigned char s_nzm[NGR];
    __shared__ int s_cnt[NM];
    __shared__ int s_start[NM];
    const int t = threadIdx.x;

    cudaGridDependencySynchronize();   // wait for prep_freq writes

    {   // per-granule 4-channel weights + nonzero mask
        const int g = t;
        const int mb = g_mi[4 * g];
        float wv[4][4];
#pragma unroll
        for (int c = 0; c < 4; c++)
#pragma unroll
            for (int e = 0; e < 4; e++) wv[c][e] = 0.0f;
#pragma unroll
        for (int e = 0; e < 4; e++) {
            int f = 4 * g + e;
            int c0 = g_mi[f] - mb;
            if (c0 < 0) c0 = 0;
            if (c0 > 2) c0 = 2;
            wv[c0][e]     += g_w0[f];
            wv[c0 + 1][e] += g_w1[f];
        }
        unsigned char nz = 0;
#pragma unroll
        for (int c = 0; c < 4; c++) {
            float4 v = make_float4(wv[c][0], wv[c][1], wv[c][2], wv[c][3]);
            g_wv[g * 4 + c] = v;
            if (v.x != 0.0f || v.y != 0.0f || v.z != 0.0f || v.w != 0.0f)
                nz |= (unsigned char)(1u << c);
        }
        s_mb[g] = mb;
        s_nzm[g] = nz;
        g_mb[g] = mb | ((int)nz << 8);
    }
    __syncthreads();

    // per-mel contiguous granule range via binary search over monotone s_mb
    int glo = 0, ghi = 0;
    if (t < NM) {
        const int m = t;
        int a = 0, b = NGR;
        while (a < b) {                     // first g with mb[g] >= m-3
            int mid = (a + b) >> 1;
            if (s_mb[mid] < m - 3) a = mid + 1; else b = mid;
        }
        glo = a;
        b = NGR;                            // first g with mb[g] > m
        while (a < b) {
            int mid = (a + b) >> 1;
            if (s_mb[mid] <= m) a = mid + 1; else b = mid;
        }
        ghi = a;
        int n = 0;
        for (int g = glo; g < ghi; g++) {
            int c = m - s_mb[g];
            if (c >= 0 && c < 4 && ((s_nzm[g] >> c) & 1)) n++;
        }
        s_cnt[t] = n;
    }
    __syncthreads();
    if (t == 0) {
        int acc = 0;
        for (int m = 0; m < NM; m++) { s_start[m] = acc; acc += s_cnt[m]; }
    }
    __syncthreads();
    if (t < NM) {
        const int m = t;
        int idx = s_start[t];
        g_redmeta[t] = s_start[t] | (s_cnt[t] << 16);
        for (int g = glo; g < ghi; g++) {   // g-ascending: deterministic order
            int c = m - s_mb[g];
            if (c >= 0 && c < 4 && ((s_nzm[g] >> c) & 1))
                g_list[idx++] = (unsigned short)(c * NGR + g);
        }
    }
}

// ---------------------------------------------------------------------------
// Main (frozen R13 math, PDL secondary): prep-independent init (spec_init
// loads, identity arithmetic) runs BEFORE the grid-dependency sync, hiding
// prep_sched + launch latency behind DRAM loads.
// ---------------------------------------------------------------------------
__global__ __launch_bounds__(NTHREADS, 3)
void invmel_main(const float* __restrict__ melspec,
                 const float* __restrict__ spec_init,
                 float* __restrict__ out) {
    __shared__ float4 s_p[4 * NGR + 1];       // partials [c][g] x 4 rows + zero slot
    __shared__ float4 s_diff[NDIFF];          // diff[mel] x 4 rows

    const float cINV = 2.0f / (float)(NB * TT);

    const int tid  = threadIdx.x;
    const int row0 = blockIdx.x * ROWS;
    const int b    = row0 / TT;
    const int t0   = row0 % TT;

    // ---- prep-independent: packed row state loads (DRAM, high MLP) ----
    u64 sp01[4], sp23[4], rb01[4], rb23[4];
#pragma unroll
    for (int e = 0; e < 4; e++) {
        float v0 = spec_init[(size_t)(row0 + 0) * NF + 4 * tid + e];
        float v1 = spec_init[(size_t)(row0 + 1) * NF + 4 * tid + e];
        float v2 = spec_init[(size_t)(row0 + 2) * NF + 4 * tid + e];
        float v3 = spec_init[(size_t)(row0 + 3) * NF + 4 * tid + e];
        PK2(sp01[e], v0, v1);
        PK2(sp23[e], v2, v3);
        rb01[e] = 0ull;
        rb23[e] = 0ull;
    }
    u64 kMOM, kNINV, kNLR;
    PK2(kMOM, 0.9f, 0.9f);
    PK2(kNINV, -cINV, -cINV);
    PK2(kNLR, -0.3f, -0.3f);

    // ---- prep-independent: reducer identity arithmetic ----
    const int lane = tid & 31;
    const int wrp  = tid >> 5;
    const int mel  = (lane >> 1) * 8 + wrp;
    const bool evenlane = ((lane & 1) == 0);
    const float4* melp = (const float4*)&melspec[((size_t)b * NM + mel) * TT + t0];

    if (tid == 0) s_p[DUMMY] = make_float4(0.f, 0.f, 0.f, 0.f);
    if (tid < NDIFF - NM) s_diff[NM + tid] = make_float4(0.f, 0.f, 0.f, 0.f);

    // ---- wait for preps; then read schedule data ----
    cudaGridDependencySynchronize();

    u64 wpk[4][4];
#pragma unroll
    for (int c = 0; c < 4; c++) {
        float4 v = g_wv[tid * 4 + c];
        PK2(wpk[c][0], v.x, v.x);
        PK2(wpk[c][1], v.y, v.y);
        PK2(wpk[c][2], v.z, v.z);
        PK2(wpk[c][3], v.w, v.w);
    }
    const int gmv = g_mb[tid];
    const int mb  = gmv & 255;
    const unsigned nzm = (unsigned)(gmv >> 8);

    const int rm = g_redmeta[mel];
    const int rs = rm & 0xFFFF;
    const int rn = rm >> 16;
    const int h  = (rn + 1) >> 1;
    const int ts = evenlane ? rs : rs + h;
    const int te = evenlane ? rs + h : rs + rn;

    unsigned short myi[8];
#pragma unroll
    for (int j = 0; j < 8; j++)
        myi[j] = (ts + j < te) ? __ldg(&g_list[ts + j]) : (unsigned short)DUMMY;
    uint4 Lx;
    Lx.x = (unsigned)myi[0] | ((unsigned)myi[1] << 16);
    Lx.y = (unsigned)myi[2] | ((unsigned)myi[3] << 16);
    Lx.z = (unsigned)myi[4] | ((unsigned)myi[5] << 16);
    Lx.w = (unsigned)myi[6] | ((unsigned)myi[7] << 16);
    __syncthreads();

    for (int it = 0; it < ITERS; it++) {
        // ---- P1: channel partials; store only nonzero channels ----
#pragma unroll
        for (int c = 0; c < 4; c++) {
            u64 a01, a23;
            F2MUL(a01, wpk[c][0], sp01[0]);
            F2MUL(a23, wpk[c][0], sp23[0]);
#pragma unroll
            for (int e = 1; e < 4; e++) {
                F2FMA(a01, wpk[c][e], sp01[e], a01);
                F2FMA(a23, wpk[c][e], sp23[e], a23);
            }
            if (nzm & (1u << c)) {
                ulonglong2 stv; stv.x = a01; stv.y = a23;
                *(ulonglong2*)&s_p[c * NGR + tid] = stv;
            }
        }
        __syncthreads();

        // ---- P2: 8 pipelined LDS.128 + pairwise tree ----
        ulonglong2 q0 = *(const ulonglong2*)&s_p[Lx.x & 0xFFFF];
        ulonglong2 q1 = *(const ulonglong2*)&s_p[Lx.x >> 16];
        ulonglong2 q2 = *(const ulonglong2*)&s_p[Lx.y & 0xFFFF];
        ulonglong2 q3 = *(const ulonglong2*)&s_p[Lx.y >> 16];
        ulonglong2 q4 = *(const ulonglong2*)&s_p[Lx.z & 0xFFFF];
        ulonglong2 q5 = *(const ulonglong2*)&s_p[Lx.z >> 16];
        ulonglong2 q6 = *(const ulonglong2*)&s_p[Lx.w & 0xFFFF];
        ulonglong2 q7 = *(const ulonglong2*)&s_p[Lx.w >> 16];
        u64 a01, a23, tA, tB, tC, tD;
        F2ADD(tA, q0.x, q1.x); F2ADD(tB, q2.x, q3.x);
        F2ADD(tC, q4.x, q5.x); F2ADD(tD, q6.x, q7.x);
        F2ADD(tA, tA, tB);     F2ADD(tC, tC, tD);
        F2ADD(a01, tA, tC);
        F2ADD(tA, q0.y, q1.y); F2ADD(tB, q2.y, q3.y);
        F2ADD(tC, q4.y, q5.y); F2ADD(tD, q6.y, q7.y);
        F2ADD(tA, tA, tB);     F2ADD(tC, tC, tD);
        F2ADD(a23, tA, tC);

        float ax, ay, az, aw;
        UPK2(ax, ay, a01);
        UPK2(az, aw, a23);
        ax += __shfl_xor_sync(0xFFFFFFFFu, ax, 1);
        ay += __shfl_xor_sync(0xFFFFFFFFu, ay, 1);
        az += __shfl_xor_sync(0xFFFFFFFFu, az, 1);
        aw += __shfl_xor_sync(0xFFFFFFFFu, aw, 1);
        if (evenlane) {
            float4 mv = __ldg(melp);  // L1-resident after iter 0
            s_diff[mel] = make_float4(mv.x - ax, mv.y - ay, mv.z - az, mv.w - aw);
        }
        __syncthreads();

        // ---- P3: grad + momentum + clamp ----
        ulonglong2 d0 = *(const ulonglong2*)&s_diff[mb + 0];
        ulonglong2 d1 = *(const ulonglong2*)&s_diff[mb + 1];
        ulonglong2 d2 = *(const ulonglong2*)&s_diff[mb + 2];
        ulonglong2 d3 = *(const ulonglong2*)&s_diff[mb + 3];
#pragma unroll
        for (int e = 0; e < 4; e++) {
            u64 g01, g23;
            F2MUL(g01, wpk[0][e], d0.x);
            F2MUL(g23, wpk[0][e], d0.y);
            F2FMA(g01, wpk[1][e], d1.x, g01);
            F2FMA(g23, wpk[1][e], d1.y, g23);
            F2FMA(g01, wpk[2][e], d2.x, g01);
            F2FMA(g23, wpk[2][e], d2.y, g23);
            F2FMA(g01, wpk[3][e], d3.x, g01);
            F2FMA(g23, wpk[3][e], d3.y, g23);
            u64 t01, t23;
            F2MUL(t01, kNINV, g01);
            F2MUL(t23, kNINV, g23);
            F2FMA(rb01[e], kMOM, rb01[e], t01);
            F2FMA(rb23[e], kMOM, rb23[e], t23);
            u64 s01, s23;
            F2FMA(s01, kNLR, rb01[e], sp01[e]);
            F2FMA(s23, kNLR, rb23[e], sp23[e]);
            float lo, hi;
            UPK2(lo, hi, s01);
            PK2(sp01[e], fmaxf(lo, 0.0f), fmaxf(hi, 0.0f));
            UPK2(lo, hi, s23);
            PK2(sp23[e], fmaxf(lo, 0.0f), fmaxf(hi, 0.0f));
        }
        // no barrier: next P1 rewrites s_p (read before last barrier);
        // s_diff rewritten only after the next iteration's first barrier.
    }

    // ---- output: one 16B store per owned f ----
#pragma unroll
    for (int e = 0; e < 4; e++) {
        ulonglong2 v; v.x = sp01[e]; v.y = sp23[e];   // rows 0,1,2,3
        *(ulonglong2*)&out[((size_t)b * NF + 4 * tid + e) * TT + t0] = v;
    }
    if (tid < ROWS) {   // f = 1024: zero fb row -> passthrough of init (>=0)
        out[((size_t)b * NF + 1024) * TT + t0 + tid] =
            spec_init[(size_t)(row0 + tid) * NF + 1024];
    }
}

// ---------------------------------------------------------------------------
extern "C" void kernel_launch(void* const* d_in, const int* in_sizes, int n_in,
                              void* d_out, int out_size) {
    const float* melspec = nullptr;
    const float* spec_init = nullptr;
    const float* fb = nullptr;
    for (int i = 0; i < n_in; i++) {
        if (in_sizes[i] == NB * NM * TT)      melspec   = (const float*)d_in[i];
        else if (in_sizes[i] == NB * TT * NF) spec_init = (const float*)d_in[i];
        else if (in_sizes[i] == NF * NM)      fb        = (const float*)d_in[i];
    }
    float* out = (float*)d_out;

    prep_freq<<<(NF * 32 + 255) / 256, 256>>>(fb);

    cudaLaunchAttribute attr[1];
    attr[0].id = cudaLaunchAttributeProgrammaticStreamSerialization;
    attr[0].val.programmaticStreamSerializationAllowed = 1;

    {   // prep_sched: PDL secondary of prep_freq
        cudaLaunchConfig_t cfg = {};
        cfg.gridDim  = dim3(1, 1, 1);
        cfg.blockDim = dim3(NTHREADS, 1, 1);
        cfg.attrs    = attr;
        cfg.numAttrs = 1;
        cudaLaunchKernelEx(&cfg, prep_sched);
    }
    {   // invmel_main: PDL secondary of prep_sched
        cudaLaunchConfig_t cfg = {};
        cfg.gridDim  = dim3(NBLOCKS, 1, 1);
        cfg.blockDim = dim3(NTHREADS, 1, 1);
        cfg.attrs    = attr;
        cfg.numAttrs = 1;
        cudaLaunchKernelEx(&cfg, invmel_main, melspec, spec_init, out);
    }
}

// round 17
// speedup vs baseline: 1.2312x; 1.0921x over previous
#include <cuda_runtime.h>
#include <cstddef>
#include <cstdint>

#define NF 1025
#define NM 128
#define NB 4
#define TT 1024
#define ROWS 4
#define NTHREADS 256
#define ITERS 20
#define NBLOCKS ((NB * TT) / ROWS)   // 1024
#define NGR 256
#define LISTCAP 1024
#define NDIFF 131
#define DUMMY 1024                   // zero slot in s_p (never written by P1)

typedef unsigned long long u64;

#define F2FMA(d,a,b,c) asm("fma.rn.f32x2 %0, %1, %2, %3;" : "=l"(d) : "l"(a), "l"(b), "l"(c))
#define F2MUL(d,a,b)   asm("mul.rn.f32x2 %0, %1, %2;"     : "=l"(d) : "l"(a), "l"(b))
#define F2ADD(d,a,b)   asm("add.rn.f32x2 %0, %1, %2;"     : "=l"(d) : "l"(a), "l"(b))
#define PK2(d,lo,hi)   asm("mov.b64 %0, {%1, %2};" : "=l"(d) : "f"(lo), "f"(hi))
#define UPK2(lo,hi,s)  asm("mov.b64 {%0, %1}, %2;" : "=f"(lo), "=f"(hi) : "l"(s))

__device__ float  g_w0[NF];
__device__ float  g_w1[NF];
__device__ int    g_mi[NF];
__device__ float4 g_wv[NGR * 4];        // [g][c] channel weight vectors
__device__ int    g_mb[NGR];            // base mel | nzm<<8 per granule
__device__ unsigned short g_list[LISTCAP];  // term idx = c*NGR + g, per mel
__device__ int    g_redmeta[NM];        // start | count<<16

// ---------------------------------------------------------------------------
// Prep 1 (fast, validated): warp per frequency row. Explicit PDL trigger
// after the global writes so prep_sched can launch during our drain.
// ---------------------------------------------------------------------------
__global__ void prep_freq(const float* __restrict__ fb) {
    int gw   = (blockIdx.x * blockDim.x + threadIdx.x) >> 5;
    int lane = threadIdx.x & 31;
    if (gw < NF) {
        const float4 v = ((const float4*)(fb + (size_t)gw * NM))[lane];
        int cand = 128;
        if (v.w > 0.0f) cand = lane * 4 + 3;
        if (v.z > 0.0f) cand = lane * 4 + 2;
        if (v.y > 0.0f) cand = lane * 4 + 1;
        if (v.x > 0.0f) cand = lane * 4;
#pragma unroll
        for (int o = 16; o; o >>= 1) {
            int other = __shfl_xor_sync(0xFFFFFFFFu, cand, o);
            cand = (other < cand) ? other : cand;
        }
        int mi = cand;
        float w0 = 0.0f, w1 = 0.0f;
        if (mi < 128) {
            int e0 = mi & 3;
            float my0 = (e0 == 0) ? v.x : (e0 == 1) ? v.y : (e0 == 2) ? v.z : v.w;
            w0 = __shfl_sync(0xFFFFFFFFu, my0, mi >> 2);
            int m1 = mi + 1;
            if (m1 < 128) {
                int e1 = m1 & 3;
                float my1 = (e1 == 0) ? v.x : (e1 == 1) ? v.y : (e1 == 2) ? v.z : v.w;
                w1 = __shfl_sync(0xFFFFFFFFu, my1, m1 >> 2);
            }
        } else mi = 0;
        if (lane == 0) { g_mi[gw] = mi; g_w0[gw] = w0; g_w1[gw] = w1; }
    }
    cudaTriggerProgrammaticLaunchCompletion();
}

// ---------------------------------------------------------------------------
// Prep 2 (single block, PDL secondary): binary-search schedule (R15).
// ---------------------------------------------------------------------------
__global__ void prep_sched() {
    __shared__ int s_mb[NGR];
    __shared__ unsigned char s_nzm[NGR];
    __shared__ int s_cnt[NM];
    __shared__ int s_start[NM];
    const int t = threadIdx.x;

    cudaGridDependencySynchronize();   // wait for prep_freq writes

    {   // per-granule 4-channel weights + nonzero mask
        const int g = t;
        const int mb = g_mi[4 * g];
        float wv[4][4];
#pragma unroll
        for (int c = 0; c < 4; c++)
#pragma unroll
            for (int e = 0; e < 4; e++) wv[c][e] = 0.0f;
#pragma unroll
        for (int e = 0; e < 4; e++) {
            int f = 4 * g + e;
            int c0 = g_mi[f] - mb;
            if (c0 < 0) c0 = 0;
            if (c0 > 2) c0 = 2;
            wv[c0][e]     += g_w0[f];
            wv[c0 + 1][e] += g_w1[f];
        }
        unsigned char nz = 0;
#pragma unroll
        for (int c = 0; c < 4; c++) {
            float4 v = make_float4(wv[c][0], wv[c][1], wv[c][2], wv[c][3]);
            g_wv[g * 4 + c] = v;
            if (v.x != 0.0f || v.y != 0.0f || v.z != 0.0f || v.w != 0.0f)
                nz |= (unsigned char)(1u << c);
        }
        s_mb[g] = mb;
        s_nzm[g] = nz;
        g_mb[g] = mb | ((int)nz << 8);
    }
    __syncthreads();

    // per-mel contiguous granule range via binary search over monotone s_mb
    int glo = 0, ghi = 0;
    if (t < NM) {
        const int m = t;
        int a = 0, b = NGR;
        while (a < b) {                     // first g with mb[g] >= m-3
            int mid = (a + b) >> 1;
            if (s_mb[mid] < m - 3) a = mid + 1; else b = mid;
        }
        glo = a;
        b = NGR;                            // first g with mb[g] > m
        while (a < b) {
            int mid = (a + b) >> 1;
            if (s_mb[mid] <= m) a = mid + 1; else b = mid;
        }
        ghi = a;
        int n = 0;
        for (int g = glo; g < ghi; g++) {
            int c = m - s_mb[g];
            if (c >= 0 && c < 4 && ((s_nzm[g] >> c) & 1)) n++;
        }
        s_cnt[t] = n;
    }
    __syncthreads();
    if (t == 0) {
        int acc = 0;
        for (int m = 0; m < NM; m++) { s_start[m] = acc; acc += s_cnt[m]; }
    }
    __syncthreads();
    if (t < NM) {
        const int m = t;
        int idx = s_start[t];
        g_redmeta[t] = s_start[t] | (s_cnt[t] << 16);
        for (int g = glo; g < ghi; g++) {   // g-ascending: deterministic order
            int c = m - s_mb[g];
            if (c >= 0 && c < 4 && ((s_nzm[g] >> c) & 1))
                g_list[idx++] = (unsigned short)(c * NGR + g);
        }
    }
    cudaTriggerProgrammaticLaunchCompletion();
}

// ---------------------------------------------------------------------------
// Main (frozen R13 math, PDL secondary): prep-independent init — spec_init
// AND melspec loads — issued before the grid-dependency sync; melspec held
// in registers for all 20 iterations (cold miss moved out of the convoy).
// ---------------------------------------------------------------------------
__global__ __launch_bounds__(NTHREADS, 3)
void invmel_main(const float* __restrict__ melspec,
                 const float* __restrict__ spec_init,
                 float* __restrict__ out) {
    __shared__ float4 s_p[4 * NGR + 1];       // partials [c][g] x 4 rows + zero slot
    __shared__ float4 s_diff[NDIFF];          // diff[mel] x 4 rows

    const float cINV = 2.0f / (float)(NB * TT);

    const int tid  = threadIdx.x;
    const int row0 = blockIdx.x * ROWS;
    const int b    = row0 / TT;
    const int t0   = row0 % TT;

    // ---- prep-independent: packed row state loads (DRAM, high MLP) ----
    u64 sp01[4], sp23[4], rb01[4], rb23[4];
#pragma unroll
    for (int e = 0; e < 4; e++) {
        float v0 = spec_init[(size_t)(row0 + 0) * NF + 4 * tid + e];
        float v1 = spec_init[(size_t)(row0 + 1) * NF + 4 * tid + e];
        float v2 = spec_init[(size_t)(row0 + 2) * NF + 4 * tid + e];
        float v3 = spec_init[(size_t)(row0 + 3) * NF + 4 * tid + e];
        PK2(sp01[e], v0, v1);
        PK2(sp23[e], v2, v3);
        rb01[e] = 0ull;
        rb23[e] = 0ull;
    }
    u64 kMOM, kNINV, kNLR;
    PK2(kMOM, 0.9f, 0.9f);
    PK2(kNINV, -cINV, -cINV);
    PK2(kNLR, -0.3f, -0.3f);

    // ---- prep-independent: reducer identity + melspec prefetch ----
    const int lane = tid & 31;
    const int wrp  = tid >> 5;
    const int mel  = (lane >> 1) * 8 + wrp;
    const bool evenlane = ((lane & 1) == 0);
    const float4 melv =
        __ldg((const float4*)&melspec[((size_t)b * NM + mel) * TT + t0]);

    if (tid == 0) s_p[DUMMY] = make_float4(0.f, 0.f, 0.f, 0.f);
    if (tid < NDIFF - NM) s_diff[NM + tid] = make_float4(0.f, 0.f, 0.f, 0.f);

    // ---- wait for preps; then read schedule data ----
    cudaGridDependencySynchronize();

    u64 wpk[4][4];
#pragma unroll
    for (int c = 0; c < 4; c++) {
        float4 v = g_wv[tid * 4 + c];
        PK2(wpk[c][0], v.x, v.x);
        PK2(wpk[c][1], v.y, v.y);
        PK2(wpk[c][2], v.z, v.z);
        PK2(wpk[c][3], v.w, v.w);
    }
    const int gmv = g_mb[tid];
    const int mb  = gmv & 255;
    const unsigned nzm = (unsigned)(gmv >> 8);

    const int rm = g_redmeta[mel];
    const int rs = rm & 0xFFFF;
    const int rn = rm >> 16;
    const int h  = (rn + 1) >> 1;
    const int ts = evenlane ? rs : rs + h;
    const int te = evenlane ? rs + h : rs + rn;

    unsigned short myi[8];
#pragma unroll
    for (int j = 0; j < 8; j++)
        myi[j] = (ts + j < te) ? __ldg(&g_list[ts + j]) : (unsigned short)DUMMY;
    uint4 Lx;
    Lx.x = (unsigned)myi[0] | ((unsigned)myi[1] << 16);
    Lx.y = (unsigned)myi[2] | ((unsigned)myi[3] << 16);
    Lx.z = (unsigned)myi[4] | ((unsigned)myi[5] << 16);
    Lx.w = (unsigned)myi[6] | ((unsigned)myi[7] << 16);
    __syncthreads();

    for (int it = 0; it < ITERS; it++) {
        // ---- P1: channel partials; store only nonzero channels ----
#pragma unroll
        for (int c = 0; c < 4; c++) {
            u64 a01, a23;
            F2MUL(a01, wpk[c][0], sp01[0]);
            F2MUL(a23, wpk[c][0], sp23[0]);
#pragma unroll
            for (int e = 1; e < 4; e++) {
                F2FMA(a01, wpk[c][e], sp01[e], a01);
                F2FMA(a23, wpk[c][e], sp23[e], a23);
            }
            if (nzm & (1u << c)) {
                ulonglong2 stv; stv.x = a01; stv.y = a23;
                *(ulonglong2*)&s_p[c * NGR + tid] = stv;
            }
        }
        __syncthreads();

        // ---- P2: 8 pipelined LDS.128 + pairwise tree ----
        ulonglong2 q0 = *(const ulonglong2*)&s_p[Lx.x & 0xFFFF];
        ulonglong2 q1 = *(const ulonglong2*)&s_p[Lx.x >> 16];
        ulonglong2 q2 = *(const ulonglong2*)&s_p[Lx.y & 0xFFFF];
        ulonglong2 q3 = *(const ulonglong2*)&s_p[Lx.y >> 16];
        ulonglong2 q4 = *(const ulonglong2*)&s_p[Lx.z & 0xFFFF];
        ulonglong2 q5 = *(const ulonglong2*)&s_p[Lx.z >> 16];
        ulonglong2 q6 = *(const ulonglong2*)&s_p[Lx.w & 0xFFFF];
        ulonglong2 q7 = *(const ulonglong2*)&s_p[Lx.w >> 16];
        u64 a01, a23, tA, tB, tC, tD;
        F2ADD(tA, q0.x, q1.x); F2ADD(tB, q2.x, q3.x);
        F2ADD(tC, q4.x, q5.x); F2ADD(tD, q6.x, q7.x);
        F2ADD(tA, tA, tB);     F2ADD(tC, tC, tD);
        F2ADD(a01, tA, tC);
        F2ADD(tA, q0.y, q1.y); F2ADD(tB, q2.y, q3.y);
        F2ADD(tC, q4.y, q5.y); F2ADD(tD, q6.y, q7.y);
        F2ADD(tA, tA, tB);     F2ADD(tC, tC, tD);
        F2ADD(a23, tA, tC);

        float ax, ay, az, aw;
        UPK2(ax, ay, a01);
        UPK2(az, aw, a23);
        ax += __shfl_xor_sync(0xFFFFFFFFu, ax, 1);
        ay += __shfl_xor_sync(0xFFFFFFFFu, ay, 1);
        az += __shfl_xor_sync(0xFFFFFFFFu, az, 1);
        aw += __shfl_xor_sync(0xFFFFFFFFu, aw, 1);
        if (evenlane) {
            s_diff[mel] = make_float4(melv.x - ax, melv.y - ay,
                                      melv.z - az, melv.w - aw);
        }
        __syncthreads();

        // ---- P3: grad + momentum + clamp ----
        ulonglong2 d0 = *(const ulonglong2*)&s_diff[mb + 0];
        ulonglong2 d1 = *(const ulonglong2*)&s_diff[mb + 1];
        ulonglong2 d2 = *(const ulonglong2*)&s_diff[mb + 2];
        ulonglong2 d3 = *(const ulonglong2*)&s_diff[mb + 3];
#pragma unroll
        for (int e = 0; e < 4; e++) {
            u64 g01, g23;
            F2MUL(g01, wpk[0][e], d0.x);
            F2MUL(g23, wpk[0][e], d0.y);
            F2FMA(g01, wpk[1][e], d1.x, g01);
            F2FMA(g23, wpk[1][e], d1.y, g23);
            F2FMA(g01, wpk[2][e], d2.x, g01);
            F2FMA(g23, wpk[2][e], d2.y, g23);
            F2FMA(g01, wpk[3][e], d3.x, g01);
            F2FMA(g23, wpk[3][e], d3.y, g23);
            u64 t01, t23;
            F2MUL(t01, kNINV, g01);
            F2MUL(t23, kNINV, g23);
            F2FMA(rb01[e], kMOM, rb01[e], t01);
            F2FMA(rb23[e], kMOM, rb23[e], t23);
            u64 s01, s23;
            F2FMA(s01, kNLR, rb01[e], sp01[e]);
            F2FMA(s23, kNLR, rb23[e], sp23[e]);
            float lo, hi;
            UPK2(lo, hi, s01);
            PK2(sp01[e], fmaxf(lo, 0.0f), fmaxf(hi, 0.0f));
            UPK2(lo, hi, s23);
            PK2(sp23[e], fmaxf(lo, 0.0f), fmaxf(hi, 0.0f));
        }
        // no barrier: next P1 rewrites s_p (read before last barrier);
        // s_diff rewritten only after the next iteration's first barrier.
    }

    // ---- output: one 16B store per owned f ----
#pragma unroll
    for (int e = 0; e < 4; e++) {
        ulonglong2 v; v.x = sp01[e]; v.y = sp23[e];   // rows 0,1,2,3
        *(ulonglong2*)&out[((size_t)b * NF + 4 * tid + e) * TT + t0] = v;
    }
    if (tid < ROWS) {   // f = 1024: zero fb row -> passthrough of init (>=0)
        out[((size_t)b * NF + 1024) * TT + t0 + tid] =
            spec_init[(size_t)(row0 + tid) * NF + 1024];
    }
}

// ---------------------------------------------------------------------------
extern "C" void kernel_launch(void* const* d_in, const int* in_sizes, int n_in,
                              void* d_out, int out_size) {
    const float* melspec = nullptr;
    const float* spec_init = nullptr;
    const float* fb = nullptr;
    for (int i = 0; i < n_in; i++) {
        if (in_sizes[i] == NB * NM * TT)      melspec   = (const float*)d_in[i];
        else if (in_sizes[i] == NB * TT * NF) spec_init = (const float*)d_in[i];
        else if (in_sizes[i] == NF * NM)      fb        = (const float*)d_in[i];
    }
    float* out = (float*)d_out;

    prep_freq<<<(NF * 32 + 255) / 256, 256>>>(fb);

    cudaLaunchAttribute attr[1];
    attr[0].id = cudaLaunchAttributeProgrammaticStreamSerialization;
    attr[0].val.programmaticStreamSerializationAllowed = 1;

    {   // prep_sched: PDL secondary of prep_freq
        cudaLaunchConfig_t cfg = {};
        cfg.gridDim  = dim3(1, 1, 1);
        cfg.blockDim = dim3(NTHREADS, 1, 1);
        cfg.attrs    = attr;
        cfg.numAttrs = 1;
        cudaLaunchKernelEx(&cfg, prep_sched);
    }
    {   // invmel_main: PDL secondary of prep_sched
        cudaLaunchConfig_t cfg = {};
        cfg.gridDim  = dim3(NBLOCKS, 1, 1);
        cfg.blockDim = dim3(NTHREADS, 1, 1);
        cfg.attrs    = attr;
        cfg.numAttrs = 1;
        cudaLaunchKernelEx(&cfg, invmel_main, melspec, spec_init, out);
    }
}